// round 16
// baseline (speedup 1.0000x reference)
#include <cuda_runtime.h>
#include <stdint.h>

// fx, fy : float32 [B=16, C=128, D=3, N=4096], topk=4 -> k=1024
// Output: concat(fx_sel, fy_sel), each [16,128,3,1024] float32.

#define B_ 16
#define C_ 128
#define D_ 3
#define N_ 4096
#define K_ 1024
#define BN_ (B_ * N_)

#define BATCH_STRIDE  ((long long)C_ * D_ * N_)       // 1,572,864
#define C_STRIDE      (D_ * N_)                       // 12,288
#define HALF_OUT      ((long long)B_ * C_ * D_ * K_)  // 6,291,456  (one tensor)
#define QB            (HALF_OUT / 2)                  // 8 batches of one tensor

#define NCHUNK 4                // FROZEN: validated numerics configuration
#define CPC    (C_ / NCHUNK)    // 32
#define NQ     15               // 6 means + 9 cross-moments
#define HB     8                // batches per stream-half

// Scratch (__device__ globals: allocation-free rule)
__device__ float2             g_stats[NCHUNK * NQ * BN_];  // (sum, kahan-c)
__device__ unsigned long long g_key[BN_];
__device__ unsigned           g_hist1[B_ * 256];   // zeroed by topk each run
__device__ int                g_idx[B_ * K_];

__device__ __forceinline__ void kadd(float& s, float& c, float v)
{
    float y = v - c;
    float t = s + y;
    c = (t - s) - y;
    s = t;
}

// ---------------------------------------------------------------------------
// Kernel 1: streaming stats — math BYTE-IDENTICAL to the validated 143.6us
// build (2 n per thread, NCHUNK=4); grid covers HB batches starting at b0.
// ---------------------------------------------------------------------------
__global__ __launch_bounds__(256)
void stats_kernel(const float* __restrict__ fx, const float* __restrict__ fy,
                  float2* __restrict__ stats, int b0)
{
    int n0 = (blockIdx.x * 256 + threadIdx.x) * 2;
    int b  = blockIdx.y + b0;
    int ch = blockIdx.z;
    int i  = b * N_ + n0;

    const float2* px = (const float2*)(fx + (long long)b * BATCH_STRIDE
                     + (long long)ch * CPC * C_STRIDE + n0);
    const float2* py = (const float2*)(fy + (long long)b * BATCH_STRIDE
                     + (long long)ch * CPC * C_STRIDE + n0);

    float s[NQ][2], c[NQ][2];
#pragma unroll
    for (int q = 0; q < NQ; q++) {
        s[q][0] = 0.f; s[q][1] = 0.f;
        c[q][0] = 0.f; c[q][1] = 0.f;
    }

#pragma unroll 4
    for (int cc = 0; cc < CPC; cc++) {
        float2 X0 = px[cc * (C_STRIDE / 2)];
        float2 X1 = px[cc * (C_STRIDE / 2) + N_ / 2];
        float2 X2 = px[cc * (C_STRIDE / 2) + N_];
        float2 Y0 = py[cc * (C_STRIDE / 2)];
        float2 Y1 = py[cc * (C_STRIDE / 2) + N_ / 2];
        float2 Y2 = py[cc * (C_STRIDE / 2) + N_];

        float xs[2][3] = {{X0.x, X1.x, X2.x}, {X0.y, X1.y, X2.y}};
        float ys[2][3] = {{Y0.x, Y1.x, Y2.x}, {Y0.y, Y1.y, Y2.y}};

#pragma unroll
        for (int l = 0; l < 2; l++) {
            kadd(s[0][l], c[0][l], xs[l][0]);
            kadd(s[1][l], c[1][l], xs[l][1]);
            kadd(s[2][l], c[2][l], xs[l][2]);
            kadd(s[3][l], c[3][l], ys[l][0]);
            kadd(s[4][l], c[4][l], ys[l][1]);
            kadd(s[5][l], c[5][l], ys[l][2]);

            kadd(s[6][l],  c[6][l],  xs[l][0] * ys[l][0]);
            kadd(s[7][l],  c[7][l],  xs[l][0] * ys[l][1]);
            kadd(s[8][l],  c[8][l],  xs[l][0] * ys[l][2]);
            kadd(s[9][l],  c[9][l],  xs[l][1] * ys[l][0]);
            kadd(s[10][l], c[10][l], xs[l][1] * ys[l][1]);
            kadd(s[11][l], c[11][l], xs[l][1] * ys[l][2]);
            kadd(s[12][l], c[12][l], xs[l][2] * ys[l][0]);
            kadd(s[13][l], c[13][l], xs[l][2] * ys[l][1]);
            kadd(s[14][l], c[14][l], xs[l][2] * ys[l][2]);
        }
    }

#pragma unroll
    for (int q = 0; q < NQ; q++) {
        stats[((long long)ch * NQ + q) * BN_ + i]     = make_float2(s[q][0], c[q][0]);
        stats[((long long)ch * NQ + q) * BN_ + i + 1] = make_float2(s[q][1], c[q][1]);
    }
}

// ---------------------------------------------------------------------------
// Kernel 2: combine — BYTE-IDENTICAL numerics; covers HB batches from b0.
// ---------------------------------------------------------------------------
__global__ __launch_bounds__(256)
void key_kernel(const float2* __restrict__ stats,
                unsigned long long* __restrict__ key,
                unsigned* __restrict__ hist1, int b0)
{
    int i = b0 * N_ + blockIdx.x * 256 + threadIdx.x;   // b*N + n
    int n = i & (N_ - 1);
    int b = i >> 12;

    double S[NQ];
#pragma unroll
    for (int q = 0; q < NQ; q++) {
        double acc = 0.0;
#pragma unroll
        for (int ch = 0; ch < NCHUNK; ch++) {
            float2 v = stats[((long long)ch * NQ + q) * BN_ + i];
            acc += (double)v.x + (double)v.y;
        }
        S[q] = acc;
    }

    double mx0 = S[0] * (1.0 / C_), mx1 = S[1] * (1.0 / C_), mx2 = S[2] * (1.0 / C_);
    double my0 = S[3] * (1.0 / C_), my1 = S[4] * (1.0 / C_), my2 = S[5] * (1.0 / C_);

    double nx = sqrt(mx0 * mx0 + mx1 * mx1 + mx2 * mx2) + 1e-6;
    double ny = sqrt(my0 * my0 + my1 * my1 + my2 * my2) + 1e-6;

    double p0 = mx0 / nx, p1 = mx1 / nx, p2 = mx2 / nx;
    double q0 = my0 / ny, q1 = my1 / ny, q2 = my2 / ny;

    double v0 = S[6]  * q0 + S[7]  * q1 + S[8]  * q2;
    double v1 = S[9]  * q0 + S[10] * q1 + S[11] * q2;
    double v2 = S[12] * q0 + S[13] * q1 + S[14] * q2;

    double sc = p0 * v0 + p1 * v1 + p2 * v2;

    unsigned long long u = (unsigned long long)__double_as_longlong(sc);
    u = (u & 0x8000000000000000ULL) ? ~u : (u | 0x8000000000000000ULL);
    unsigned long long k = (u & ~0xFFFULL) | (unsigned long long)(N_ - 1 - n);
    key[i] = k;

    atomicAdd(&hist1[b * 256 + (unsigned)(k >> 56)], 1u);
}

// ---------------------------------------------------------------------------
// Kernel 3: topk (validated path; warp-aggregated compaction). Covers HB
// batches from b0. Pass-0 histogram prebuilt (read, then zeroed for replay).
// ---------------------------------------------------------------------------
__global__ __launch_bounds__(1024)
void topk_kernel(const unsigned long long* __restrict__ keyg,
                 unsigned* __restrict__ hist1,
                 int* __restrict__ idxout, int b0)
{
    __shared__ unsigned long long keys[N_];    // 32 KB
    __shared__ unsigned long long skeys[K_];   // 8 KB
    __shared__ unsigned long long cand[128];
    __shared__ unsigned long long s_pivot;
    __shared__ unsigned s_hist[256];
    __shared__ unsigned s_sel[3];              // [digit, new rank, count]
    __shared__ unsigned s_cnt;

    int b = blockIdx.x + b0;
    int tid = threadIdx.x;
    int lane = tid & 31;

#pragma unroll
    for (int it = 0; it < 4; it++) {
        int n = tid + it * 1024;
        keys[n] = keyg[b * N_ + n];
    }
    if (tid == 0) s_cnt = 0;
    __syncthreads();

    unsigned long long prefix = 0;
    unsigned r = K_ - 1;
    unsigned m = N_;
    int done_shift = 64;
#pragma unroll 1
    for (int p = 0; p < 8 && m > 128; p++) {
        int shift = 56 - 8 * p;
        if (p == 0) {
            if (tid < 256) {
                s_hist[tid] = hist1[b * 256 + tid];
                hist1[b * 256 + tid] = 0;      // ready for next replay
            }
        } else {
            if (tid < 256) s_hist[tid] = 0;
            __syncthreads();
#pragma unroll
            for (int it = 0; it < 4; it++) {
                unsigned long long key = keys[tid + it * 1024];
                if (((key ^ prefix) >> (shift + 8)) == 0)
                    atomicAdd(&s_hist[(unsigned)(key >> shift) & 255u], 1u);
            }
        }
        __syncthreads();
        if (tid < 32) {
            unsigned c[8], tot = 0;
#pragma unroll
            for (int i = 0; i < 8; i++) { c[i] = s_hist[tid * 8 + i]; tot += c[i]; }
            unsigned suf = tot;
#pragma unroll
            for (int o = 1; o < 32; o <<= 1) {
                unsigned v = __shfl_down_sync(0xffffffffu, suf, o);
                if (tid + o < 32) suf += v;
            }
            unsigned above = suf - tot;
            if (above <= r && r < above + tot) {
                unsigned acc = above;
#pragma unroll
                for (int i = 7; i >= 0; i--) {
                    if (acc + c[i] > r) {
                        s_sel[0] = (unsigned)(tid * 8 + i);
                        s_sel[1] = r - acc;
                        s_sel[2] = c[i];
                        break;
                    }
                    acc += c[i];
                }
            }
        }
        __syncthreads();
        prefix |= ((unsigned long long)s_sel[0]) << shift;
        r = s_sel[1];
        m = s_sel[2];
        done_shift = shift;
        __syncthreads();
    }

    // --- compact candidates (warp-aggregated) ---
#pragma unroll
    for (int it = 0; it < 4; it++) {
        unsigned long long key = keys[tid + it * 1024];
        bool pred = ((key >> done_shift) == (prefix >> done_shift));
        unsigned mask = __ballot_sync(0xffffffffu, pred);
        unsigned cnt = __popc(mask);
        unsigned base = 0;
        if (lane == 0 && cnt) base = atomicAdd(&s_cnt, cnt);
        base = __shfl_sync(0xffffffffu, base, 0);
        if (pred) {
            unsigned off = __popc(mask & ((1u << lane) - 1u));
            cand[base + off] = key;
        }
    }
    __syncthreads();

    if (tid < m) {
        unsigned long long mykey = cand[tid];
        unsigned cnt = 0;
        for (unsigned j = 0; j < m; j++)
            cnt += (cand[j] > mykey) ? 1u : 0u;
        if (cnt == r) s_pivot = mykey;
    }
    if (tid == 0) s_cnt = 0;
    __syncthreads();
    unsigned long long pivot = s_pivot;

    // --- compact winners (warp-aggregated; sorted below) ---
#pragma unroll
    for (int it = 0; it < 4; it++) {
        unsigned long long key = keys[tid + it * 1024];
        bool pred = (key >= pivot);
        unsigned mask = __ballot_sync(0xffffffffu, pred);
        unsigned cnt = __popc(mask);
        unsigned base = 0;
        if (lane == 0 && cnt) base = atomicAdd(&s_cnt, cnt);
        base = __shfl_sync(0xffffffffu, base, 0);
        if (pred) {
            unsigned off = __popc(mask & ((1u << lane) - 1u));
            skeys[base + off] = key;
        }
    }
    __syncthreads();

    // bitonic sort of 1024 keys, descending (j<=16 via warp shuffles)
    for (int k = 2; k <= K_; k <<= 1) {
        for (int j = k >> 1; j >= 32; j >>= 1) {
            int t = tid, ixj = t ^ j;
            if (ixj > t) {
                unsigned long long a = skeys[t];
                unsigned long long c2 = skeys[ixj];
                bool desc = ((t & k) == 0);
                if (desc ? (a < c2) : (a > c2)) { skeys[t] = c2; skeys[ixj] = a; }
            }
            __syncthreads();
        }
        {
            unsigned long long v = skeys[tid];
            bool desc = ((tid & k) == 0);
            int jstart = (k >> 1) < 16 ? (k >> 1) : 16;
            for (int j = jstart; j >= 1; j >>= 1) {
                unsigned long long o = __shfl_xor_sync(0xffffffffu, v, j);
                bool lower = ((tid & j) == 0);
                bool takemax = (desc == lower);
                v = takemax ? (v > o ? v : o) : (v < o ? v : o);
            }
            skeys[tid] = v;
            __syncthreads();
        }
    }

    idxout[b * K_ + tid] = (N_ - 1) - (int)(skeys[tid] & 0xFFFULL);
}

// ---------------------------------------------------------------------------
// Kernel 4: gather for one batch-half h (batches h*8 .. h*8+7 of both fx
// and fy). float4 output vectorization (4 j per thread).
// ---------------------------------------------------------------------------
__global__ __launch_bounds__(256)
void gather_kernel(const float* __restrict__ fx, const float* __restrict__ fy,
                   const int* __restrict__ idx, float* __restrict__ out, int h)
{
    long long t = (long long)blockIdx.x * blockDim.x + threadIdx.x;
    long long e = t * 4;                 // element index within this half
    if (e >= HALF_OUT) return;           // HALF_OUT elems: 8 batches x 2 tensors

    const float* src;
    float* dst;
    long long tt = e;
    if (tt < QB) {                       // fx portion of this half
        src = fx;
        dst = out + (long long)h * QB;
    } else {                             // fy portion
        tt -= QB;
        src = fy;
        dst = out + HALF_OUT + (long long)h * QB;
    }

    int j0 = (int)(tt & (K_ - 1));       // multiple of 4
    long long rest = tt >> 10;           // (lb*C + c)*D + d
    int d = (int)(rest % D_);
    long long bcl = rest / D_;           // lb*C + c  (local batch)
    int lb = (int)(bcl >> 7);
    int cch = (int)(bcl & 127);
    int b = h * HB + lb;

    int4 nn = *(const int4*)&idx[b * K_ + j0];
    const float* row = src + (long long)b * BATCH_STRIDE
                     + (long long)cch * C_STRIDE + (long long)d * N_;

    float4 v;
    v.x = row[nn.x];
    v.y = row[nn.y];
    v.z = row[nn.z];
    v.w = row[nn.w];
    *(float4*)&dst[tt] = v;
}

// ---------------------------------------------------------------------------
extern "C" void kernel_launch(void* const* d_in, const int* in_sizes, int n_in,
                              void* d_out, int out_size)
{
    const float* fx = (const float*)d_in[0];
    const float* fy = (const float*)d_in[1];
    float* out = (float*)d_out;

    float2* stats;
    unsigned long long* key;
    unsigned* hist1;
    int* idx;
    cudaGetSymbolAddress((void**)&stats, g_stats);
    cudaGetSymbolAddress((void**)&key,   g_key);
    cudaGetSymbolAddress((void**)&hist1, g_hist1);
    cudaGetSymbolAddress((void**)&idx,   g_idx);

    // Fork a second stream (capture-legal: event fork from the default
    // stream, event join back). Streams/events are intentionally not
    // destroyed (destroying capture-participating streams before EndCapture
    // is illegal); kernel_launch runs only a handful of times.
    cudaStream_t s2;
    if (cudaStreamCreateWithFlags(&s2, cudaStreamNonBlocking) != cudaSuccess)
        s2 = 0;   // degrade to serial on the default stream
    cudaEvent_t evF = 0, evJ = 0;
    cudaEventCreateWithFlags(&evF, cudaEventDisableTiming);
    cudaEventCreateWithFlags(&evJ, cudaEventDisableTiming);

    cudaEventRecord(evF, 0);
    if (s2) cudaStreamWaitEvent(s2, evF, 0);

    dim3 g1(N_ / 512, HB, NCHUNK);       // per half: 8 x 8 x 4 blocks
    stats_kernel<<<g1, 256, 0, 0>>>(fx, fy, stats, 0);
    stats_kernel<<<g1, 256, 0, s2>>>(fx, fy, stats, HB);

    int kblocks = HB * N_ / 256;         // 128 per half
    key_kernel<<<kblocks, 256, 0, 0>>>(stats, key, hist1, 0);
    key_kernel<<<kblocks, 256, 0, s2>>>(stats, key, hist1, HB);

    topk_kernel<<<HB, 1024, 0, 0>>>(key, hist1, idx, 0);
    topk_kernel<<<HB, 1024, 0, s2>>>(key, hist1, idx, HB);

    int gblocks = (int)((HALF_OUT / 4 + 255) / 256);   // 6144 per half
    gather_kernel<<<gblocks, 256, 0, 0>>>(fx, fy, idx, out, 0);
    gather_kernel<<<gblocks, 256, 0, s2>>>(fx, fy, idx, out, 1);

    if (s2) {
        cudaEventRecord(evJ, s2);
        cudaStreamWaitEvent(0, evJ, 0);
    }
}

// round 17
// speedup vs baseline: 1.2563x; 1.2563x over previous
#include <cuda_runtime.h>
#include <stdint.h>

// fx, fy : float32 [B=16, C=128, D=3, N=4096], topk=4 -> k=1024
// Output: concat(fx_sel, fy_sel), each [16,128,3,1024] float32.
//
// This is the round-8 build (measured 143.55us, rel_err 0.0), re-banked
// verbatim after rounds 9-16 established that all four kernels sit at
// measured floors and every structural deviation regressed or was neutral.

#define B_ 16
#define C_ 128
#define D_ 3
#define N_ 4096
#define K_ 1024
#define BN_ (B_ * N_)

#define BATCH_STRIDE  ((long long)C_ * D_ * N_)       // 1,572,864
#define C_STRIDE      (D_ * N_)                       // 12,288
#define HALF_OUT      ((long long)B_ * C_ * D_ * K_)  // 6,291,456

#define NCHUNK 4                // FROZEN: validated numerics configuration
#define CPC    (C_ / NCHUNK)    // 32
#define NQ     15               // 6 means + 9 cross-moments

// Scratch (__device__ globals: allocation-free rule)
__device__ float2             g_stats[NCHUNK * NQ * BN_];  // (sum, kahan-c)
__device__ unsigned long long g_key[BN_];
__device__ unsigned           g_hist1[B_ * 256];           // pass-0 histograms
__device__ int                g_idx[B_ * K_];

__device__ __forceinline__ void kadd(float& s, float& c, float v)
{
    float y = v - c;
    float t = s + y;
    c = (t - s) - y;
    s = t;
}

// ---------------------------------------------------------------------------
// Kernel 1 (validated): streaming stats. Per (b, n-pair, chunk),
// Kahan-accumulate 6 means + 9 cross-moments over 32 c's; float2 loads.
// Block (0,0,0) zeroes g_hist1 for this replay (key_kernel runs after).
// ---------------------------------------------------------------------------
__global__ __launch_bounds__(256)
void stats_kernel(const float* __restrict__ fx, const float* __restrict__ fy,
                  float2* __restrict__ stats, unsigned* __restrict__ hist1)
{
    if (blockIdx.x == 0 && blockIdx.y == 0 && blockIdx.z == 0) {
        for (int j = threadIdx.x; j < B_ * 256; j += 256) hist1[j] = 0;
    }

    int n0 = (blockIdx.x * 256 + threadIdx.x) * 2;
    int b  = blockIdx.y;
    int ch = blockIdx.z;
    int i  = b * N_ + n0;

    const float2* px = (const float2*)(fx + (long long)b * BATCH_STRIDE
                     + (long long)ch * CPC * C_STRIDE + n0);
    const float2* py = (const float2*)(fy + (long long)b * BATCH_STRIDE
                     + (long long)ch * CPC * C_STRIDE + n0);

    float s[NQ][2], c[NQ][2];
#pragma unroll
    for (int q = 0; q < NQ; q++) {
        s[q][0] = 0.f; s[q][1] = 0.f;
        c[q][0] = 0.f; c[q][1] = 0.f;
    }

#pragma unroll 4
    for (int cc = 0; cc < CPC; cc++) {
        float2 X0 = px[cc * (C_STRIDE / 2)];
        float2 X1 = px[cc * (C_STRIDE / 2) + N_ / 2];
        float2 X2 = px[cc * (C_STRIDE / 2) + N_];
        float2 Y0 = py[cc * (C_STRIDE / 2)];
        float2 Y1 = py[cc * (C_STRIDE / 2) + N_ / 2];
        float2 Y2 = py[cc * (C_STRIDE / 2) + N_];

        float xs[2][3] = {{X0.x, X1.x, X2.x}, {X0.y, X1.y, X2.y}};
        float ys[2][3] = {{Y0.x, Y1.x, Y2.x}, {Y0.y, Y1.y, Y2.y}};

#pragma unroll
        for (int l = 0; l < 2; l++) {
            kadd(s[0][l], c[0][l], xs[l][0]);
            kadd(s[1][l], c[1][l], xs[l][1]);
            kadd(s[2][l], c[2][l], xs[l][2]);
            kadd(s[3][l], c[3][l], ys[l][0]);
            kadd(s[4][l], c[4][l], ys[l][1]);
            kadd(s[5][l], c[5][l], ys[l][2]);

            kadd(s[6][l],  c[6][l],  xs[l][0] * ys[l][0]);
            kadd(s[7][l],  c[7][l],  xs[l][0] * ys[l][1]);
            kadd(s[8][l],  c[8][l],  xs[l][0] * ys[l][2]);
            kadd(s[9][l],  c[9][l],  xs[l][1] * ys[l][0]);
            kadd(s[10][l], c[10][l], xs[l][1] * ys[l][1]);
            kadd(s[11][l], c[11][l], xs[l][1] * ys[l][2]);
            kadd(s[12][l], c[12][l], xs[l][2] * ys[l][0]);
            kadd(s[13][l], c[13][l], xs[l][2] * ys[l][1]);
            kadd(s[14][l], c[14][l], xs[l][2] * ys[l][2]);
        }
    }

#pragma unroll
    for (int q = 0; q < NQ; q++) {
        stats[((long long)ch * NQ + q) * BN_ + i]     = make_float2(s[q][0], c[q][0]);
        stats[((long long)ch * NQ + q) * BN_ + i + 1] = make_float2(s[q][1], c[q][1]);
    }
}

// ---------------------------------------------------------------------------
// Kernel 2 (validated): fp64 combine (fixed chunk order), normalize, contract
// s = p^T M q, emit sortable u64 key with (4095-n) in the low 12 bits
// (smaller index wins ties, matching jax.lax.top_k). Also builds the
// per-batch 256-bin top-digit histogram so topk skips its priciest pass.
// ---------------------------------------------------------------------------
__global__ __launch_bounds__(256)
void key_kernel(const float2* __restrict__ stats,
                unsigned long long* __restrict__ key,
                unsigned* __restrict__ hist1)
{
    int i = blockIdx.x * 256 + threadIdx.x;   // b*N + n
    int n = i & (N_ - 1);
    int b = i >> 12;

    double S[NQ];
#pragma unroll
    for (int q = 0; q < NQ; q++) {
        double acc = 0.0;
#pragma unroll
        for (int ch = 0; ch < NCHUNK; ch++) {
            float2 v = stats[((long long)ch * NQ + q) * BN_ + i];
            acc += (double)v.x + (double)v.y;
        }
        S[q] = acc;
    }

    double mx0 = S[0] * (1.0 / C_), mx1 = S[1] * (1.0 / C_), mx2 = S[2] * (1.0 / C_);
    double my0 = S[3] * (1.0 / C_), my1 = S[4] * (1.0 / C_), my2 = S[5] * (1.0 / C_);

    double nx = sqrt(mx0 * mx0 + mx1 * mx1 + mx2 * mx2) + 1e-6;
    double ny = sqrt(my0 * my0 + my1 * my1 + my2 * my2) + 1e-6;

    double p0 = mx0 / nx, p1 = mx1 / nx, p2 = mx2 / nx;
    double q0 = my0 / ny, q1 = my1 / ny, q2 = my2 / ny;

    double v0 = S[6]  * q0 + S[7]  * q1 + S[8]  * q2;
    double v1 = S[9]  * q0 + S[10] * q1 + S[11] * q2;
    double v2 = S[12] * q0 + S[13] * q1 + S[14] * q2;

    double sc = p0 * v0 + p1 * v1 + p2 * v2;

    unsigned long long u = (unsigned long long)__double_as_longlong(sc);
    u = (u & 0x8000000000000000ULL) ? ~u : (u | 0x8000000000000000ULL);
    unsigned long long k = (u & ~0xFFFULL) | (unsigned long long)(N_ - 1 - n);
    key[i] = k;

    atomicAdd(&hist1[b * 256 + (unsigned)(k >> 56)], 1u);
}

// ---------------------------------------------------------------------------
// Kernel 3 (validated): topk. Pass-0 histogram prebuilt; radix passes until
// <=128 candidates, brute-force pivot, compact 1024 winners, bitonic sort
// with warp-register phases for j<=16.
// ---------------------------------------------------------------------------
__global__ __launch_bounds__(1024)
void topk_kernel(const unsigned long long* __restrict__ keyg,
                 const unsigned* __restrict__ hist1,
                 int* __restrict__ idxout)
{
    __shared__ unsigned long long keys[N_];    // 32 KB
    __shared__ unsigned long long skeys[K_];   // 8 KB
    __shared__ unsigned long long cand[128];
    __shared__ unsigned long long s_pivot;
    __shared__ unsigned s_hist[256];
    __shared__ unsigned s_sel[3];              // [digit, new rank, count]
    __shared__ unsigned s_cnt;

    int b = blockIdx.x;
    int tid = threadIdx.x;

#pragma unroll
    for (int it = 0; it < 4; it++) {
        int n = tid + it * 1024;
        keys[n] = keyg[b * N_ + n];
    }
    if (tid == 0) s_cnt = 0;
    __syncthreads();

    unsigned long long prefix = 0;
    unsigned r = K_ - 1;
    unsigned m = N_;
    int done_shift = 64;
#pragma unroll 1
    for (int p = 0; p < 8 && m > 128; p++) {
        int shift = 56 - 8 * p;
        if (p == 0) {
            if (tid < 256) s_hist[tid] = hist1[b * 256 + tid];
        } else {
            if (tid < 256) s_hist[tid] = 0;
            __syncthreads();
#pragma unroll
            for (int it = 0; it < 4; it++) {
                unsigned long long key = keys[tid + it * 1024];
                if (((key ^ prefix) >> (shift + 8)) == 0)
                    atomicAdd(&s_hist[(unsigned)(key >> shift) & 255u], 1u);
            }
        }
        __syncthreads();
        if (tid < 32) {
            unsigned c[8], tot = 0;
#pragma unroll
            for (int i = 0; i < 8; i++) { c[i] = s_hist[tid * 8 + i]; tot += c[i]; }
            unsigned suf = tot;
#pragma unroll
            for (int o = 1; o < 32; o <<= 1) {
                unsigned v = __shfl_down_sync(0xffffffffu, suf, o);
                if (tid + o < 32) suf += v;
            }
            unsigned above = suf - tot;
            if (above <= r && r < above + tot) {
                unsigned acc = above;
#pragma unroll
                for (int i = 7; i >= 0; i--) {
                    if (acc + c[i] > r) {
                        s_sel[0] = (unsigned)(tid * 8 + i);
                        s_sel[1] = r - acc;
                        s_sel[2] = c[i];
                        break;
                    }
                    acc += c[i];
                }
            }
        }
        __syncthreads();
        prefix |= ((unsigned long long)s_sel[0]) << shift;
        r = s_sel[1];
        m = s_sel[2];
        done_shift = shift;
        __syncthreads();
    }

#pragma unroll
    for (int it = 0; it < 4; it++) {
        unsigned long long key = keys[tid + it * 1024];
        if ((key >> done_shift) == (prefix >> done_shift)) {
            unsigned pos = atomicAdd(&s_cnt, 1u);
            cand[pos] = key;
        }
    }
    __syncthreads();

    if (tid < m) {
        unsigned long long mykey = cand[tid];
        unsigned cnt = 0;
        for (unsigned j = 0; j < m; j++)
            cnt += (cand[j] > mykey) ? 1u : 0u;
        if (cnt == r) s_pivot = mykey;
    }
    if (tid == 0) s_cnt = 0;
    __syncthreads();
    unsigned long long pivot = s_pivot;

#pragma unroll
    for (int it = 0; it < 4; it++) {
        unsigned long long key = keys[tid + it * 1024];
        if (key >= pivot) {
            unsigned pos = atomicAdd(&s_cnt, 1u);
            skeys[pos] = key;
        }
    }
    __syncthreads();

    for (int k = 2; k <= K_; k <<= 1) {
        for (int j = k >> 1; j >= 32; j >>= 1) {
            int t = tid, ixj = t ^ j;
            if (ixj > t) {
                unsigned long long a = skeys[t];
                unsigned long long c2 = skeys[ixj];
                bool desc = ((t & k) == 0);
                if (desc ? (a < c2) : (a > c2)) { skeys[t] = c2; skeys[ixj] = a; }
            }
            __syncthreads();
        }
        {
            unsigned long long v = skeys[tid];
            bool desc = ((tid & k) == 0);
            int jstart = (k >> 1) < 16 ? (k >> 1) : 16;
            for (int j = jstart; j >= 1; j >>= 1) {
                unsigned long long o = __shfl_xor_sync(0xffffffffu, v, j);
                bool lower = ((tid & j) == 0);
                bool takemax = (desc == lower);
                v = takemax ? (v > o ? v : o) : (v < o ? v : o);
            }
            skeys[tid] = v;
            __syncthreads();
        }
    }

    idxout[b * K_ + tid] = (N_ - 1) - (int)(skeys[tid] & 0xFFFULL);
}

// ---------------------------------------------------------------------------
// Kernel 4 (validated): gather, float4 output vectorization (4 j per thread).
// ---------------------------------------------------------------------------
__global__ __launch_bounds__(256)
void gather_kernel(const float* __restrict__ fx, const float* __restrict__ fy,
                   const int* __restrict__ idx, float* __restrict__ out)
{
    long long t = (long long)blockIdx.x * blockDim.x + threadIdx.x;
    long long e = t * 4;                 // element index (multiple of 4)
    if (e >= 2 * HALF_OUT) return;

    const float* src = fx;
    float* dst = out;
    long long tt = e;
    if (tt >= HALF_OUT) {
        tt -= HALF_OUT;
        src = fy;
        dst = out + HALF_OUT;
    }

    int j0 = (int)(tt & (K_ - 1));       // multiple of 4
    long long rest = tt >> 10;           // (b*C + c)*D + d
    int d = (int)(rest % D_);
    long long bc = rest / D_;            // b*C + c
    int b = (int)(bc >> 7);

    int4 nn = *(const int4*)&idx[b * K_ + j0];
    const float* row = src + bc * (long long)C_STRIDE + (long long)d * N_;

    float4 v;
    v.x = row[nn.x];
    v.y = row[nn.y];
    v.z = row[nn.z];
    v.w = row[nn.w];
    *(float4*)&dst[tt] = v;
}

// ---------------------------------------------------------------------------
extern "C" void kernel_launch(void* const* d_in, const int* in_sizes, int n_in,
                              void* d_out, int out_size)
{
    const float* fx = (const float*)d_in[0];
    const float* fy = (const float*)d_in[1];
    float* out = (float*)d_out;

    float2* stats;
    unsigned long long* key;
    unsigned* hist1;
    int* idx;
    cudaGetSymbolAddress((void**)&stats, g_stats);
    cudaGetSymbolAddress((void**)&key,   g_key);
    cudaGetSymbolAddress((void**)&hist1, g_hist1);
    cudaGetSymbolAddress((void**)&idx,   g_idx);

    dim3 g1(N_ / 512, B_, NCHUNK);       // 2 n per thread
    stats_kernel<<<g1, 256>>>(fx, fy, stats, hist1);

    key_kernel<<<BN_ / 256, 256>>>(stats, key, hist1);

    topk_kernel<<<B_, 1024>>>(key, hist1, idx);

    long long total_vec = (2 * HALF_OUT) / 4;
    int blocks = (int)((total_vec + 255) / 256);
    gather_kernel<<<blocks, 256>>>(fx, fy, idx, out);
}